// round 2
// baseline (speedup 1.0000x reference)
#include <cuda_runtime.h>
#include <math.h>

#define N_NODES 16384
#define F_DIM   256
#define EPS_NORM 1e-12f

// ---------------- scratch (allocation-free: __device__ globals) ----------------
__device__ float g_dinv[N_NODES];                 // 1/sqrt(deg)
__device__ float g_sfeat[N_NODES * F_DIM];        // dinv[k] * feat[k][n]
__device__ float g_agg[N_NODES * F_DIM];          // feat_agg

// ---------------- kernel 1: row sums of A (+1 for the I), dinv = rsqrt -------
__global__ void __launch_bounds__(256) rowsum_kernel(const float* __restrict__ A) {
    const int row = blockIdx.x;
    const float4* arow = reinterpret_cast<const float4*>(A + (size_t)row * N_NODES);
    float s = 0.f;
    #pragma unroll 4
    for (int i = threadIdx.x; i < N_NODES / 4; i += 256) {
        float4 v = arow[i];
        s += (v.x + v.y) + (v.z + v.w);
    }
    // block reduce
    __shared__ float red[8];
    #pragma unroll
    for (int o = 16; o > 0; o >>= 1) s += __shfl_down_sync(0xffffffffu, s, o);
    if ((threadIdx.x & 31) == 0) red[threadIdx.x >> 5] = s;
    __syncthreads();
    if (threadIdx.x < 32) {
        s = (threadIdx.x < 8) ? red[threadIdx.x] : 0.f;
        #pragma unroll
        for (int o = 4; o > 0; o >>= 1) s += __shfl_down_sync(0xffffffffu, s, o);
        if (threadIdx.x == 0) g_dinv[row] = rsqrtf(s + 1.0f);
    }
}

// ---------------- kernel 2: sfeat[k][n] = dinv[k] * feat[k][n] ---------------
__global__ void __launch_bounds__(256) scale_feat_kernel(const float* __restrict__ feat) {
    int idx = blockIdx.x * 256 + threadIdx.x;            // float4 index
    const int total = N_NODES * F_DIM / 4;
    if (idx < total) {
        int row = idx / (F_DIM / 4);
        float di = g_dinv[row];
        float4 v = reinterpret_cast<const float4*>(feat)[idx];
        v.x *= di; v.y *= di; v.z *= di; v.w *= di;
        reinterpret_cast<float4*>(g_sfeat)[idx] = v;
    }
}

// ---------------- kernel 3: GEMM1  agg = dinv_i*(A @ sfeat) + dinv_i^2*feat --
// BM=128, BN=128, BK=16, thread tile 8x8, 256 threads (16x16)
__global__ void __launch_bounds__(256) gemm1_kernel(const float* __restrict__ A,
                                                    const float* __restrict__ feat) {
    const int BM = 128, BN = 128, BK = 16, TM = 8, TN = 8;
    __shared__ float As[BK][BM + 1];   // transposed A tile, padded
    __shared__ float Bs[BK][BN];

    const int tid = threadIdx.x;
    const int tn = tid & 15;           // 0..15
    const int tm = tid >> 4;           // 0..15
    const int m0 = blockIdx.y * BM;
    const int n0 = blockIdx.x * BN;

    // A-tile loader: 128 rows x 16 cols = 512 float4, 2 per thread
    const int a_r = tid >> 2;          // 0..63
    const int a_c = (tid & 3) * 4;     // 0,4,8,12
    // B-tile loader: 16 rows x 128 cols = 512 float4, 2 per thread
    const int b_r = tid >> 5;          // 0..7
    const int b_c = (tid & 31) * 4;

    float acc[TM][TN] = {};
    float ar[TM], br[TN];

    for (int k0 = 0; k0 < N_NODES; k0 += BK) {
        #pragma unroll
        for (int s = 0; s < 2; s++) {
            int r = a_r + s * 64;
            float4 v = *reinterpret_cast<const float4*>(
                &A[(size_t)(m0 + r) * N_NODES + k0 + a_c]);
            As[a_c + 0][r] = v.x;
            As[a_c + 1][r] = v.y;
            As[a_c + 2][r] = v.z;
            As[a_c + 3][r] = v.w;
        }
        #pragma unroll
        for (int s = 0; s < 2; s++) {
            int r = b_r + s * 8;
            *reinterpret_cast<float4*>(&Bs[r][b_c]) =
                *reinterpret_cast<const float4*>(
                    &g_sfeat[(size_t)(k0 + r) * F_DIM + n0 + b_c]);
        }
        __syncthreads();
        #pragma unroll
        for (int k = 0; k < BK; k++) {
            #pragma unroll
            for (int i = 0; i < TM; i++) ar[i] = As[k][tm * TM + i];
            #pragma unroll
            for (int j = 0; j < TN; j++) br[j] = Bs[k][tn * TN + j];
            #pragma unroll
            for (int i = 0; i < TM; i++)
                #pragma unroll
                for (int j = 0; j < TN; j++)
                    acc[i][j] = fmaf(ar[i], br[j], acc[i][j]);
        }
        __syncthreads();
    }

    // epilogue: agg = dinv_i * acc + dinv_i^2 * feat
    #pragma unroll
    for (int i = 0; i < TM; i++) {
        int gi = m0 + tm * TM + i;
        float di = g_dinv[gi];
        float di2 = di * di;
        #pragma unroll
        for (int j = 0; j < TN; j++) {
            int gn = n0 + tn * TN + j;
            g_agg[(size_t)gi * F_DIM + gn] =
                di * acc[i][j] + di2 * feat[(size_t)gi * F_DIM + gn];
        }
    }
}

// ---------------- kernel 4: out = l2norm_rows(relu(agg @ W)) -----------------
// BM=64, BN=256 (full width -> whole row in one block so we can normalize),
// BK=16 over K=256; threads 256 as 8(m) x 32(n), thread tile 8x8.
__global__ void __launch_bounds__(256) gemm2_norm_kernel(const float* __restrict__ W,
                                                         float* __restrict__ out) {
    const int BM = 64, BN = 256, BK = 16, TM = 8, TN = 8;
    __shared__ float As[BK][BM + 1];
    __shared__ float Bs[BK][BN];
    __shared__ float s_ssq[BM];

    const int tid = threadIdx.x;
    const int tn = tid & 31;           // 0..31
    const int tm = tid >> 5;           // 0..7
    const int m0 = blockIdx.x * BM;

    if (tid < BM) s_ssq[tid] = 0.f;

    // A-tile loader: 64 x 16 = 256 float4, 1 per thread
    const int a_r = tid >> 2;          // 0..63
    const int a_c = (tid & 3) * 4;
    // B-tile loader: 16 x 256 = 1024 float4, 4 per thread
    const int b_r = tid >> 6;          // 0..3
    const int b_c = (tid & 63) * 4;

    float acc[TM][TN] = {};
    float ar[TM], br[TN];

    for (int k0 = 0; k0 < F_DIM; k0 += BK) {
        {
            float4 v = *reinterpret_cast<const float4*>(
                &g_agg[(size_t)(m0 + a_r) * F_DIM + k0 + a_c]);
            As[a_c + 0][a_r] = v.x;
            As[a_c + 1][a_r] = v.y;
            As[a_c + 2][a_r] = v.z;
            As[a_c + 3][a_r] = v.w;
        }
        #pragma unroll
        for (int s = 0; s < 4; s++) {
            int r = b_r + s * 4;
            *reinterpret_cast<float4*>(&Bs[r][b_c]) =
                *reinterpret_cast<const float4*>(&W[(size_t)(k0 + r) * F_DIM + b_c]);
        }
        __syncthreads();
        #pragma unroll
        for (int k = 0; k < BK; k++) {
            #pragma unroll
            for (int i = 0; i < TM; i++) ar[i] = As[k][tm * TM + i];
            #pragma unroll
            for (int j = 0; j < TN; j++) br[j] = Bs[k][tn * TN + j];
            #pragma unroll
            for (int i = 0; i < TM; i++)
                #pragma unroll
                for (int j = 0; j < TN; j++)
                    acc[i][j] = fmaf(ar[i], br[j], acc[i][j]);
        }
        __syncthreads();
    }

    // relu + per-row sum of squares
    #pragma unroll
    for (int i = 0; i < TM; i++) {
        float ss = 0.f;
        #pragma unroll
        for (int j = 0; j < TN; j++) {
            float v = fmaxf(acc[i][j], 0.f);
            acc[i][j] = v;
            ss = fmaf(v, v, ss);
        }
        atomicAdd(&s_ssq[tm * TM + i], ss);
    }
    __syncthreads();

    // normalize: x / max(||x||, eps)
    #pragma unroll
    for (int i = 0; i < TM; i++) {
        int gi = m0 + tm * TM + i;
        float nrm = sqrtf(s_ssq[tm * TM + i]);
        float sc = 1.0f / fmaxf(nrm, EPS_NORM);
        #pragma unroll
        for (int j = 0; j < TN; j++) {
            int gn = tn * TN + j;
            out[(size_t)gi * F_DIM + gn] = acc[i][j] * sc;
        }
    }
}

// ---------------- launch ------------------------------------------------------
extern "C" void kernel_launch(void* const* d_in, const int* in_sizes, int n_in,
                              void* d_out, int out_size) {
    // Identify inputs by element count (robust to ordering):
    // feat: 16384*256 = 4194304, A: 16384*16384 = 268435456, W: 256*256 = 65536
    const float* feat = nullptr;
    const float* A = nullptr;
    const float* W = nullptr;
    for (int i = 0; i < n_in; i++) {
        long long sz = (long long)in_sizes[i];
        if (sz == (long long)N_NODES * N_NODES)      A   = (const float*)d_in[i];
        else if (sz == (long long)N_NODES * F_DIM)   feat = (const float*)d_in[i];
        else if (sz == (long long)F_DIM * F_DIM)     W   = (const float*)d_in[i];
    }
    float* out = (float*)d_out;

    // 1. degrees -> dinv
    rowsum_kernel<<<N_NODES, 256>>>(A);
    // 2. column-scaled features
    scale_feat_kernel<<<(N_NODES * F_DIM / 4 + 255) / 256, 256>>>(feat);
    // 3. big GEMM + fused diagonal/row-scale epilogue
    {
        dim3 grid(F_DIM / 128, N_NODES / 128);   // (2, 128)
        gemm1_kernel<<<grid, 256>>>(A, feat);
    }
    // 4. projection + relu + row L2 normalize
    gemm2_norm_kernel<<<N_NODES / 64, 256>>>(W, out);
}

// round 5
// speedup vs baseline: 3.5627x; 3.5627x over previous
#include <cuda_runtime.h>
#include <math.h>
#include <stdint.h>

#define N_NODES 16384
#define F_DIM   256
#define EPS_NORM 1e-12f

// ---------------- scratch (allocation-free: __device__ globals) ----------------
__device__ float g_dinv[N_NODES];            // 1/sqrt(deg)
__device__ float g_sfeatT[F_DIM * N_NODES];  // tf32_rn(dinv[k]*feat[k][n]), [n][k] K-major
__device__ float g_agg[N_NODES * F_DIM];     // feat_agg

// ============================ PTX helpers (sm_80+ portable) ==================
__device__ __forceinline__ uint32_t smem_to_u32(const void* p) {
    uint32_t a;
    asm("{ .reg .u64 t; cvta.to.shared.u64 t, %1; cvt.u32.u64 %0, t; }" : "=r"(a) : "l"(p));
    return a;
}

#define LDSM_X4(r0, r1, r2, r3, addr) \
    asm volatile("ldmatrix.sync.aligned.m8n8.x4.shared.b16 {%0,%1,%2,%3}, [%4];" \
        : "=r"(r0), "=r"(r1), "=r"(r2), "=r"(r3) : "r"(addr))

#define MMA_TF32(d, a, b) \
    asm volatile("mma.sync.aligned.m16n8k8.row.col.f32.tf32.tf32.f32 " \
        "{%0,%1,%2,%3}, {%4,%5,%6,%7}, {%8,%9}, {%0,%1,%2,%3};" \
        : "+f"((d)[0]), "+f"((d)[1]), "+f"((d)[2]), "+f"((d)[3]) \
        : "r"((a)[0]), "r"((a)[1]), "r"((a)[2]), "r"((a)[3]), \
          "r"((b)[0]), "r"((b)[1]))

#define CP_ASYNC_16(dst, src) \
    asm volatile("cp.async.cg.shared.global [%0], [%1], 16;" :: "r"(dst), "l"(src))
#define CP_ASYNC_COMMIT() asm volatile("cp.async.commit_group;" ::: "memory")
#define CP_ASYNC_WAIT_1() asm volatile("cp.async.wait_group 1;" ::: "memory")

__device__ __forceinline__ uint32_t tf32_rn_bits(uint32_t b) {
    float f = __uint_as_float(b);
    uint32_t r;
    asm("cvt.rna.tf32.f32 %0, %1;" : "=r"(r) : "f"(f));
    return r;
}

// ---------------- kernel 1: row sums of A (+1 for I), dinv = rsqrt ----------
__global__ void __launch_bounds__(256) rowsum_kernel(const float* __restrict__ A) {
    const int row = blockIdx.x;
    const float4* arow = reinterpret_cast<const float4*>(A + (size_t)row * N_NODES);
    float s = 0.f;
    #pragma unroll 4
    for (int i = threadIdx.x; i < N_NODES / 4; i += 256) {
        float4 v = arow[i];
        s += (v.x + v.y) + (v.z + v.w);
    }
    __shared__ float red[8];
    #pragma unroll
    for (int o = 16; o > 0; o >>= 1) s += __shfl_down_sync(0xffffffffu, s, o);
    if ((threadIdx.x & 31) == 0) red[threadIdx.x >> 5] = s;
    __syncthreads();
    if (threadIdx.x < 32) {
        s = (threadIdx.x < 8) ? red[threadIdx.x] : 0.f;
        #pragma unroll
        for (int o = 4; o > 0; o >>= 1) s += __shfl_down_sync(0xffffffffu, s, o);
        if (threadIdx.x == 0) g_dinv[row] = rsqrtf(s + 1.0f);
    }
}

// ---------------- kernel 2: sfeatT[n][k] = tf32_rn(dinv[k] * feat[k][n]) ----
__global__ void __launch_bounds__(256) transpose_scale_kernel(const float* __restrict__ feat) {
    __shared__ float t[32][33];
    const int k0 = blockIdx.x * 32;
    const int n0 = blockIdx.y * 32;
    const int tx = threadIdx.x, ty = threadIdx.y;
    #pragma unroll
    for (int i = 0; i < 4; i++) {
        int k = k0 + ty + i * 8;
        t[ty + i * 8][tx] = g_dinv[k] * feat[(size_t)k * F_DIM + n0 + tx];
    }
    __syncthreads();
    #pragma unroll
    for (int i = 0; i < 4; i++) {
        int n = n0 + ty + i * 8;
        uint32_t b = tf32_rn_bits(__float_as_uint(t[tx][ty + i * 8]));
        g_sfeatT[(size_t)n * N_NODES + k0 + tx] = __uint_as_float(b);
    }
}

// ---------------- kernel 3: GEMM1 via mma.sync tf32 --------------------------
// C[16384,256] = A @ sfeatT^T ; agg = dinv_i*C + dinv_i^2*feat
// CTA tile 128x128x32, 3-stage cp.async pipeline, 8 warps (2m x 4n), warp 64x32.
#define G1_BK       32
#define G1_KT       (N_NODES / G1_BK)          /* 512 */
#define G1_ROWB     144                        /* 32 floats + 16B pad */
#define G1_TILEB    (128 * G1_ROWB)            /* 18432 per A or B tile */
#define G1_STAGEB   (2 * G1_TILEB)             /* 36864 */
#define G1_SMEM     (3 * G1_STAGEB)            /* 110592 */

__device__ __forceinline__ void g1_load_stage(uint32_t sbuf, const float* __restrict__ A,
                                              const float* __restrict__ BT,
                                              int m0, int n0, int kt, int tid) {
    const int k0 = kt * G1_BK;
    #pragma unroll
    for (int i = 0; i < 4; i++) {
        int id = tid + i * 256;
        int row = id >> 3, c = id & 7;
        uint32_t dst = sbuf + row * G1_ROWB + c * 16;
        const float* src = A + (size_t)(m0 + row) * N_NODES + k0 + c * 4;
        CP_ASYNC_16(dst, src);
    }
    #pragma unroll
    for (int i = 0; i < 4; i++) {
        int id = tid + i * 256;
        int row = id >> 3, c = id & 7;
        uint32_t dst = sbuf + G1_TILEB + row * G1_ROWB + c * 16;
        const float* src = BT + (size_t)(n0 + row) * N_NODES + k0 + c * 4;
        CP_ASYNC_16(dst, src);
    }
}

__global__ void __launch_bounds__(256, 2) gemm1_mma_kernel(const float* __restrict__ A,
                                                           const float* __restrict__ feat) {
    extern __shared__ __align__(128) char smem[];
    const uint32_t sb = smem_to_u32(smem);
    const int tid = threadIdx.x;
    const int lane = tid & 31;
    const int wid = tid >> 5;
    const int m0 = blockIdx.y * 128;
    const int n0 = blockIdx.x * 128;
    const int wm0 = (wid >> 2) * 64;   // warp m offset in CTA tile
    const int wn0 = (wid & 3) * 32;    // warp n offset

    float acc[4][4][4];
    #pragma unroll
    for (int i = 0; i < 4; i++)
        #pragma unroll
        for (int j = 0; j < 4; j++)
            #pragma unroll
            for (int t = 0; t < 4; t++) acc[i][j][t] = 0.f;

    // ldmatrix per-thread base addresses (stage 0, kstep 0)
    uint32_t aBase[4], bBase[2];
    {
        const int seg = lane >> 3;
        // A (m-major [m][k]): x4 matrices = {rows m..m+7 kLo, m+8..m+15 kLo, m..m+7 kHi, m+8..15 kHi}
        const int rA = (lane & 7) + ((seg & 1) << 3);
        const int cA = seg >> 1;
        #pragma unroll
        for (int i = 0; i < 4; i++)
            aBase[i] = sb + (uint32_t)(wm0 + i * 16 + rA) * G1_ROWB + cA * 16;
        // B (n-major [n][k]): x4 = {nTile even b0, even b1, odd b0, odd b1}
        const int rB = (lane & 7) + ((seg >> 1) << 3);
        const int cB = seg & 1;
        #pragma unroll
        for (int j = 0; j < 2; j++)
            bBase[j] = sb + G1_TILEB + (uint32_t)(wn0 + j * 16 + rB) * G1_ROWB + cB * 16;
    }

    // prologue: stages 0,1
    g1_load_stage(sb + 0 * G1_STAGEB, A, g_sfeatT, m0, n0, 0, tid);
    CP_ASYNC_COMMIT();
    g1_load_stage(sb + 1 * G1_STAGEB, A, g_sfeatT, m0, n0, 1, tid);
    CP_ASYNC_COMMIT();

    int stage = 0;
    #pragma unroll 1
    for (int kt = 0; kt < G1_KT; kt++) {
        CP_ASYNC_WAIT_1();
        __syncthreads();

        const int nk = kt + 2;
        if (nk < G1_KT) {
            int ns = nk - (nk / 3) * 3;
            g1_load_stage(sb + ns * G1_STAGEB, A, g_sfeatT, m0, n0, nk, tid);
        }
        CP_ASYNC_COMMIT();

        const uint32_t so = stage * G1_STAGEB;
        #pragma unroll
        for (int ks = 0; ks < 4; ks++) {
            uint32_t a[4][4], b[4][2];
            #pragma unroll
            for (int i = 0; i < 4; i++)
                LDSM_X4(a[i][0], a[i][1], a[i][2], a[i][3], aBase[i] + so + ks * 32);
            #pragma unroll
            for (int j = 0; j < 2; j++)
                LDSM_X4(b[2 * j][0], b[2 * j][1], b[2 * j + 1][0], b[2 * j + 1][1],
                        bBase[j] + so + ks * 32);
            #pragma unroll
            for (int i = 0; i < 4; i++)
                #pragma unroll
                for (int j = 0; j < 4; j++)
                    MMA_TF32(acc[i][j], a[i], b[j]);
        }
        stage++; if (stage == 3) stage = 0;
    }

    // epilogue: agg = dinv_m * acc + dinv_m^2 * feat
    const int r = lane >> 2;
    const int c2 = (lane & 3) * 2;
    #pragma unroll
    for (int i = 0; i < 4; i++) {
        #pragma unroll
        for (int half = 0; half < 2; half++) {
            const int m = m0 + wm0 + i * 16 + r + half * 8;
            const float di = g_dinv[m];
            const float di2 = di * di;
            #pragma unroll
            for (int j = 0; j < 4; j++) {
                const int n = n0 + wn0 + j * 8 + c2;
                float2 fv = *reinterpret_cast<const float2*>(&feat[(size_t)m * F_DIM + n]);
                float2 o;
                o.x = di * acc[i][j][half * 2 + 0] + di2 * fv.x;
                o.y = di * acc[i][j][half * 2 + 1] + di2 * fv.y;
                *reinterpret_cast<float2*>(&g_agg[(size_t)m * F_DIM + n]) = o;
            }
        }
    }
}

// ---------------- kernel 4: out = l2norm_rows(relu(agg @ W)) -----------------
__global__ void __launch_bounds__(256) gemm2_norm_kernel(const float* __restrict__ W,
                                                         float* __restrict__ out) {
    const int BM = 64, BN = 256, BK = 16, TM = 8, TN = 8;
    __shared__ float As[BK][BM + 1];
    __shared__ float Bs[BK][BN];
    __shared__ float s_ssq[BM];

    const int tid = threadIdx.x;
    const int tn = tid & 31;
    const int tm = tid >> 5;
    const int m0 = blockIdx.x * BM;

    if (tid < BM) s_ssq[tid] = 0.f;

    const int a_r = tid >> 2;
    const int a_c = (tid & 3) * 4;
    const int b_r = tid >> 6;
    const int b_c = (tid & 63) * 4;

    float acc[TM][TN] = {};
    float ar[TM], br[TN];

    for (int k0 = 0; k0 < F_DIM; k0 += BK) {
        {
            float4 v = *reinterpret_cast<const float4*>(
                &g_agg[(size_t)(m0 + a_r) * F_DIM + k0 + a_c]);
            As[a_c + 0][a_r] = v.x;
            As[a_c + 1][a_r] = v.y;
            As[a_c + 2][a_r] = v.z;
            As[a_c + 3][a_r] = v.w;
        }
        #pragma unroll
        for (int s = 0; s < 4; s++) {
            int r = b_r + s * 4;
            *reinterpret_cast<float4*>(&Bs[r][b_c]) =
                *reinterpret_cast<const float4*>(&W[(size_t)(k0 + r) * F_DIM + b_c]);
        }
        __syncthreads();
        #pragma unroll
        for (int k = 0; k < BK; k++) {
            #pragma unroll
            for (int i = 0; i < TM; i++) ar[i] = As[k][tm * TM + i];
            #pragma unroll
            for (int j = 0; j < TN; j++) br[j] = Bs[k][tn * TN + j];
            #pragma unroll
            for (int i = 0; i < TM; i++)
                #pragma unroll
                for (int j = 0; j < TN; j++)
                    acc[i][j] = fmaf(ar[i], br[j], acc[i][j]);
        }
        __syncthreads();
    }

    #pragma unroll
    for (int i = 0; i < TM; i++) {
        float ss = 0.f;
        #pragma unroll
        for (int j = 0; j < TN; j++) {
            float v = fmaxf(acc[i][j], 0.f);
            acc[i][j] = v;
            ss = fmaf(v, v, ss);
        }
        atomicAdd(&s_ssq[tm * TM + i], ss);
    }
    __syncthreads();

    #pragma unroll
    for (int i = 0; i < TM; i++) {
        int gi = m0 + tm * TM + i;
        float nrm = sqrtf(s_ssq[tm * TM + i]);
        float sc = 1.0f / fmaxf(nrm, EPS_NORM);
        #pragma unroll
        for (int j = 0; j < TN; j++) {
            int gn = tn * TN + j;
            out[(size_t)gi * F_DIM + gn] = acc[i][j] * sc;
        }
    }
}

// ---------------- host launch -------------------------------------------------
extern "C" void kernel_launch(void* const* d_in, const int* in_sizes, int n_in,
                              void* d_out, int out_size) {
    const float* feat = nullptr;
    const float* A = nullptr;
    const float* W = nullptr;
    for (int i = 0; i < n_in; i++) {
        long long sz = (long long)in_sizes[i];
        if (sz == (long long)N_NODES * N_NODES)      A    = (const float*)d_in[i];
        else if (sz == (long long)N_NODES * F_DIM)   feat = (const float*)d_in[i];
        else if (sz == (long long)F_DIM * F_DIM)     W    = (const float*)d_in[i];
    }
    float* out = (float*)d_out;

    static bool attr_set = false;
    if (!attr_set) {
        cudaFuncSetAttribute(gemm1_mma_kernel,
                             cudaFuncAttributeMaxDynamicSharedMemorySize, G1_SMEM);
        attr_set = true;
    }

    // 1. degrees -> dinv
    rowsum_kernel<<<N_NODES, 256>>>(A);
    // 2. transposed, dinv-scaled, tf32-RN-rounded features (B operand, K-major)
    {
        dim3 grid(N_NODES / 32, F_DIM / 32);
        transpose_scale_kernel<<<grid, dim3(32, 8)>>>(feat);
    }
    // 3. tensor-core GEMM + fused epilogue
    {
        dim3 grid(F_DIM / 128, N_NODES / 128);   // (2, 128) = 256 CTAs, 1 wave @ 2/SM
        gemm1_mma_kernel<<<grid, 256, G1_SMEM>>>(A, feat);
    }
    // 4. projection + relu + row L2 normalize
    gemm2_norm_kernel<<<N_NODES / 64, 256>>>(W, out);
}